// round 7
// baseline (speedup 1.0000x reference)
#include <cuda_runtime.h>
#include <cuda_bf16.h>
#include <math.h>

#define B_DIM 32
#define H_DIM 56
#define W_DIM 56
#define C_DIM 256
#define HW (H_DIM * W_DIM)             // 3136
#define NPIX (B_DIM * HW)              // 100352

#define BAND 4                          // rows per CTA
#define BANDS_PER_IMG (H_DIM / BAND)    // 14
#define TROWS (BAND + 6)                // 10 pooled rows incl. halo
#define TCOLS (W_DIM + 6)               // 62 pooled cols incl. halo
#define BAND_PIX (BAND * W_DIM)         // 224
#define POOL_PIX (TROWS * W_DIM)        // 560
#define BAND_F4 (BAND_PIX * (C_DIM/4))  // 14336 float4 per band

// ---------------------------------------------------------------------------
// Single fused kernel. One CTA = one 4-row band of one image.
//  Phase 1: pool band+halo (10 rows x 56 px) -> smem tile (zero-padded).
//           Halo rows are re-pooled by neighbor CTAs too; dupes hit L2.
//  Phase 2: 7x7 conv + sigmoid -> smem attn (224 px).
//  Phase 3: scale: re-read own x band (L1/L2-hot, read ~us ago) * attn -> out.
// x touches DRAM exactly once; out written once (__stcs so out allocations
// don't evict still-needed x lines from L2).
// ---------------------------------------------------------------------------
__global__ void __launch_bounds__(256) fused_kernel(
    const float* __restrict__ x,
    const float* __restrict__ w,     // [7,7,2,1] HWIO
    const float* __restrict__ bias,  // [1]
    float* __restrict__ out)
{
    __shared__ float2 tile[TROWS][TCOLS];
    __shared__ float  attn_s[BAND_PIX];
    __shared__ float  ws[98];
    __shared__ float  bs;

    const int img  = blockIdx.x / BANDS_PER_IMG;
    const int band = blockIdx.x - img * BANDS_PER_IMG;
    const int r0   = band * BAND;

    const int tid  = threadIdx.x;
    const int wid  = tid >> 5;
    const int lane = tid & 31;
    const int sub  = lane >> 3;      // pixel within warp group (0..3)
    const int co   = lane & 7;       // float4 slot (0..7)

    // weights/bias + zero the halo columns of the tile
    if (tid < 98) ws[tid] = w[tid];
    if (tid == 104) bs = bias[0];
    if (tid >= 128 && tid < 128 + TROWS * 6) {
        int z = tid - 128;
        int r = z / 6;
        int c = z % 6;
        tile[r][c < 3 ? c : (TCOLS - 6 + c)] = make_float2(0.0f, 0.0f);
    }

    // ---------- Phase 1: pool 10 rows (band + 3/3 halo) ----------
    const size_t img_base = (size_t)img * HW;

    for (int p0 = 0; p0 < POOL_PIX; p0 += 32) {
        int p = p0 + wid * 4 + sub;            // 8 warps x 4 px = 32 px/iter
        if (p < POOL_PIX) {
            int lr = p / W_DIM;                // 0..9
            int lc = p - lr * W_DIM;           // 0..55
            int gy = r0 - 3 + lr;

            if (gy >= 0 && gy < H_DIM) {
                const float4* __restrict__ xr =
                    (const float4*)(x + (img_base + (size_t)gy * W_DIM + lc) * C_DIM);
                float4 v0 = xr[co];
                float4 v1 = xr[co + 8];
                float4 v2 = xr[co + 16];
                float4 v3 = xr[co + 24];
                float4 v4 = xr[co + 32];
                float4 v5 = xr[co + 40];
                float4 v6 = xr[co + 48];
                float4 v7 = xr[co + 56];

                float s = (((v0.x+v0.y)+(v0.z+v0.w)) + ((v1.x+v1.y)+(v1.z+v1.w)))
                        + (((v2.x+v2.y)+(v2.z+v2.w)) + ((v3.x+v3.y)+(v3.z+v3.w)))
                        + (((v4.x+v4.y)+(v4.z+v4.w)) + ((v5.x+v5.y)+(v5.z+v5.w)))
                        + (((v6.x+v6.y)+(v6.z+v6.w)) + ((v7.x+v7.y)+(v7.z+v7.w)));

                float m01 = fmaxf(fmaxf(fmaxf(v0.x,v0.y), fmaxf(v0.z,v0.w)),
                                  fmaxf(fmaxf(v1.x,v1.y), fmaxf(v1.z,v1.w)));
                float m23 = fmaxf(fmaxf(fmaxf(v2.x,v2.y), fmaxf(v2.z,v2.w)),
                                  fmaxf(fmaxf(v3.x,v3.y), fmaxf(v3.z,v3.w)));
                float m45 = fmaxf(fmaxf(fmaxf(v4.x,v4.y), fmaxf(v4.z,v4.w)),
                                  fmaxf(fmaxf(v5.x,v5.y), fmaxf(v5.z,v5.w)));
                float m67 = fmaxf(fmaxf(fmaxf(v6.x,v6.y), fmaxf(v6.z,v6.w)),
                                  fmaxf(fmaxf(v7.x,v7.y), fmaxf(v7.z,v7.w)));
                float m = fmaxf(fmaxf(m01, m23), fmaxf(m45, m67));

                #pragma unroll
                for (int off = 4; off; off >>= 1) {
                    s += __shfl_xor_sync(0xffffffffu, s, off);
                    m = fmaxf(m, __shfl_xor_sync(0xffffffffu, m, off));
                }

                if (co == 0)
                    tile[lr][lc + 3] = make_float2(s * (1.0f / 256.0f), m);
            } else {
                if (co == 0)
                    tile[lr][lc + 3] = make_float2(0.0f, 0.0f);
            }
        }
    }
    __syncthreads();

    // ---------- Phase 2: 7x7 conv + sigmoid ----------
    if (tid < BAND_PIX) {
        int y  = tid / W_DIM;      // 0..3
        int xc = tid - y * W_DIM;  // 0..55
        float acc = bs;
        #pragma unroll
        for (int dy = 0; dy < 7; dy++) {
            #pragma unroll
            for (int dx = 0; dx < 7; dx++) {
                float2 p = tile[y + dy][xc + dx];
                acc = fmaf(p.x, ws[(dy * 7 + dx) * 2 + 0], acc);
                acc = fmaf(p.y, ws[(dy * 7 + dx) * 2 + 1], acc);
            }
        }
        attn_s[tid] = 1.0f / (1.0f + __expf(-acc));
    }
    __syncthreads();

    // ---------- Phase 3: scale own band (x is L1/L2-hot) ----------
    const size_t base_f4 = (img_base + (size_t)r0 * W_DIM) * (C_DIM / 4);
    const float4* __restrict__ xr = (const float4*)x;
    float4* __restrict__ o = (float4*)out;

    #pragma unroll
    for (int k = 0; k < BAND_F4 / 256; k += 8) {       // 56 iters, 8-batched
        float4 v[8];
        float  a[8];
        #pragma unroll
        for (int j = 0; j < 8; j++)
            v[j] = xr[base_f4 + tid + (size_t)(k + j) * 256];
        #pragma unroll
        for (int j = 0; j < 8; j++)
            a[j] = attn_s[(tid + (k + j) * 256) >> 6];
        #pragma unroll
        for (int j = 0; j < 8; j++) {
            v[j].x *= a[j]; v[j].y *= a[j]; v[j].z *= a[j]; v[j].w *= a[j];
        }
        #pragma unroll
        for (int j = 0; j < 8; j++)
            __stcs(&o[base_f4 + tid + (size_t)(k + j) * 256], v[j]);
    }
}

extern "C" void kernel_launch(void* const* d_in, const int* in_sizes, int n_in,
                              void* d_out, int out_size) {
    const float* x  = (const float*)d_in[0];
    const float* w  = (const float*)d_in[1];
    const float* b  = (const float*)d_in[2];
    float* out = (float*)d_out;

    const int blocks = B_DIM * BANDS_PER_IMG;   // 448
    fused_kernel<<<blocks, 256>>>(x, w, b, out);
}

// round 8
// speedup vs baseline: 1.2151x; 1.2151x over previous
#include <cuda_runtime.h>
#include <cuda_bf16.h>
#include <math.h>

#define B_DIM 32
#define H_DIM 56
#define W_DIM 56
#define C_DIM 256
#define NPIX (B_DIM * H_DIM * W_DIM)   // 100352
#define HW (H_DIM * W_DIM)             // 3136
#define ROW_F4 (W_DIM * (C_DIM / 4))   // 3584 float4 per image-row

// Scratch (no cudaMalloc allowed): pooled [avg,max] per pixel.
__device__ float2 g_pooled[NPIX];

// ---------------------------------------------------------------------------
// Kernel 1: channel mean+max pool. 4 pixels per warp, 8 lanes per pixel.
// 4 front-batched 32B loads per lane; per instruction the warp reads
// 8 fully-used 128B lines, coalesced. (Proven 18.9us @ 5.65TB/s.)
// ---------------------------------------------------------------------------
struct f8 { float4 a, b; };
__device__ __forceinline__ f8 ldg_f8(const float* p) {
    f8 r;
    unsigned long long d0, d1, d2, d3;
    asm volatile("ld.global.v4.b64 {%0,%1,%2,%3}, [%4];"
                 : "=l"(d0), "=l"(d1), "=l"(d2), "=l"(d3)
                 : "l"(p));
    r.a.x = __uint_as_float((unsigned)(d0));
    r.a.y = __uint_as_float((unsigned)(d0 >> 32));
    r.a.z = __uint_as_float((unsigned)(d1));
    r.a.w = __uint_as_float((unsigned)(d1 >> 32));
    r.b.x = __uint_as_float((unsigned)(d2));
    r.b.y = __uint_as_float((unsigned)(d2 >> 32));
    r.b.z = __uint_as_float((unsigned)(d3));
    r.b.w = __uint_as_float((unsigned)(d3 >> 32));
    return r;
}

__global__ void __launch_bounds__(256) pool_kernel(const float* __restrict__ x) {
    int warp = (blockIdx.x * blockDim.x + threadIdx.x) >> 5;
    int lane = threadIdx.x & 31;
    int sub  = lane >> 3;          // which of the warp's 4 pixels
    int co   = lane & 7;           // 32B slot within pixel
    int pix  = warp * 4 + sub;
    if (pix >= NPIX) return;

    const float* __restrict__ xr = x + (size_t)pix * C_DIM;
    f8 u0 = ldg_f8(xr + co * 8);
    f8 u1 = ldg_f8(xr + co * 8 + 64);
    f8 u2 = ldg_f8(xr + co * 8 + 128);
    f8 u3 = ldg_f8(xr + co * 8 + 192);

    float4 v0 = u0.a, v1 = u0.b, v2 = u1.a, v3 = u1.b;
    float4 v4 = u2.a, v5 = u2.b, v6 = u3.a, v7 = u3.b;

    float s = (((v0.x + v0.y) + (v0.z + v0.w)) + ((v1.x + v1.y) + (v1.z + v1.w)))
            + (((v2.x + v2.y) + (v2.z + v2.w)) + ((v3.x + v3.y) + (v3.z + v3.w)))
            + (((v4.x + v4.y) + (v4.z + v4.w)) + ((v5.x + v5.y) + (v5.z + v5.w)))
            + (((v6.x + v6.y) + (v6.z + v6.w)) + ((v7.x + v7.y) + (v7.z + v7.w)));

    float m01 = fmaxf(fmaxf(fmaxf(v0.x, v0.y), fmaxf(v0.z, v0.w)),
                      fmaxf(fmaxf(v1.x, v1.y), fmaxf(v1.z, v1.w)));
    float m23 = fmaxf(fmaxf(fmaxf(v2.x, v2.y), fmaxf(v2.z, v2.w)),
                      fmaxf(fmaxf(v3.x, v3.y), fmaxf(v3.z, v3.w)));
    float m45 = fmaxf(fmaxf(fmaxf(v4.x, v4.y), fmaxf(v4.z, v4.w)),
                      fmaxf(fmaxf(v5.x, v5.y), fmaxf(v5.z, v5.w)));
    float m67 = fmaxf(fmaxf(fmaxf(v6.x, v6.y), fmaxf(v6.z, v6.w)),
                      fmaxf(fmaxf(v7.x, v7.y), fmaxf(v7.z, v7.w)));
    float m = fmaxf(fmaxf(m01, m23), fmaxf(m45, m67));

    #pragma unroll
    for (int off = 4; off; off >>= 1) {
        s += __shfl_xor_sync(0xffffffffu, s, off);
        m = fmaxf(m, __shfl_xor_sync(0xffffffffu, m, off));
    }

    if (co == 0) {
        g_pooled[pix] = make_float2(s * (1.0f / 256.0f), m);
    }
}

// ---------------------------------------------------------------------------
// Kernel 2: fused conv + sigmoid + scale. One CTA per image-row.
//  Warps 0-1: 7x7 SAME conv for the row's 56 pixels, reading g_pooled
//             directly (tiny, L2-hot) -> attn_s in smem.
//  Then all 256 threads stream the row's 56KB of x (reverse CTA order for
//  L2 reuse from the pool pass; __ldcs last-use / __stcs writes).
// ---------------------------------------------------------------------------
__global__ void __launch_bounds__(256) conv_scale_kernel(
    const float* __restrict__ x,
    const float* __restrict__ w,     // [7,7,2,1] HWIO
    const float* __restrict__ bias,  // [1]
    float* __restrict__ out)
{
    __shared__ float attn_s[W_DIM];

    // reverse order: tail of x (most recently pooled, L2-resident) first
    int rb  = gridDim.x - 1 - blockIdx.x;
    int img = rb / H_DIM;
    int row = rb - img * H_DIM;

    const int tid = threadIdx.x;

    // ---- conv phase: threads 0..55, one pixel each ----
    if (tid < W_DIM) {
        const float2* __restrict__ pooled_b = g_pooled + img * HW;
        float acc = __ldg(bias);
        #pragma unroll
        for (int dy = 0; dy < 7; dy++) {
            int gy = row + dy - 3;
            if (gy >= 0 && gy < H_DIM) {
                const float2* __restrict__ prow = pooled_b + gy * W_DIM;
                #pragma unroll
                for (int dx = 0; dx < 7; dx++) {
                    int gx = tid + dx - 3;
                    if (gx >= 0 && gx < W_DIM) {
                        float2 p = __ldg(&prow[gx]);
                        acc = fmaf(p.x, __ldg(&w[(dy * 7 + dx) * 2 + 0]), acc);
                        acc = fmaf(p.y, __ldg(&w[(dy * 7 + dx) * 2 + 1]), acc);
                    }
                }
            }
        }
        attn_s[tid] = 1.0f / (1.0f + __expf(-acc));
    }
    __syncthreads();

    // ---- scale phase: stream the row's 3584 float4 (14 per thread) ----
    const size_t base = ((size_t)img * HW + (size_t)row * W_DIM) * (C_DIM / 4);
    const float4* __restrict__ xr = (const float4*)x;
    float4* __restrict__ o = (float4*)out;

    #pragma unroll
    for (int k = 0; k < 14; k += 7) {
        float4 v[7];
        float  a[7];
        #pragma unroll
        for (int j = 0; j < 7; j++)
            v[j] = __ldcs(&xr[base + tid + (size_t)(k + j) * 256]);
        #pragma unroll
        for (int j = 0; j < 7; j++)
            a[j] = attn_s[(tid + (k + j) * 256) >> 6];
        #pragma unroll
        for (int j = 0; j < 7; j++) {
            v[j].x *= a[j]; v[j].y *= a[j]; v[j].z *= a[j]; v[j].w *= a[j];
        }
        #pragma unroll
        for (int j = 0; j < 7; j++)
            __stcs(&o[base + tid + (size_t)(k + j) * 256], v[j]);
    }
}

extern "C" void kernel_launch(void* const* d_in, const int* in_sizes, int n_in,
                              void* d_out, int out_size) {
    const float* x  = (const float*)d_in[0];
    const float* w  = (const float*)d_in[1];
    const float* b  = (const float*)d_in[2];
    float* out = (float*)d_out;

    const int pool_blocks = (NPIX / 4) / 8;       // 3136
    pool_kernel<<<pool_blocks, 256>>>(x);

    const int cs_blocks = B_DIM * H_DIM;          // 1792
    conv_scale_kernel<<<cs_blocks, 256>>>(x, w, b, out);
}